// round 1
// baseline (speedup 1.0000x reference)
#include <cuda_runtime.h>
#include <math.h>

#define HH 192
#define WW 192
#define NN 6
#define HW (HH*WW)
#define KGC 20
#define KC 400          /* control points */
#define NA 403          /* system size   */
#define NC 405          /* cols incl rhs */
#define LD 416          /* padded row stride (floats) */
#define LAMBD 100.0f
#define BIGV 100000000.0f
#define EPSF 1e-9f
#define STEP (2.0f/191.0f)

// ---------------- device scratch (no allocations allowed) ----------------
__device__ float2 g_coord[NN*HW];
__device__ float2 g_delta[NN*HW];
__device__ float  g_mask [NN*HW];
__device__ float2 g_src  [NN*KC];
__device__ float  g_m    [NN*KC];
__device__ __align__(16) float g_A[NN][NA*LD];
__device__ float2 g_wgt[NN*KC];
__device__ float2 g_aff[NN*3];

__device__ __forceinline__ float gridc(int i){ return -1.0f + (float)i*STEP; }
__device__ __forceinline__ int ctrl_i(int t){
    return (int)rintf((float)t * ((float)(HH-1)/(float)(KGC-1)));
}

// ---------------- 1) backward warp (delta/coord/mask on the fly) ----------
__global__ void warp_kernel(const float* __restrict__ duv,
                            const float* __restrict__ uv,
                            float* __restrict__ out, int out_size){
    int idx = blockIdx.x*blockDim.x + threadIdx.x;
    if (idx >= NN*HW) return;
    float u = uv[idx*2+0], v = uv[idx*2+1];
    float x = (u + 1.0f)*0.5f*(float)(WW-1);
    float y = (v + 1.0f)*0.5f*(float)(HH-1);
    float x0 = floorf(x), y0 = floorf(y);
    float wx = x - x0, wy = y - y0;
    float d0=0.f,d1=0.f,c0=0.f,c1=0.f,mk=0.f;
    #pragma unroll
    for (int cy=0; cy<2; cy++){
        #pragma unroll
        for (int cx=0; cx<2; cx++){
            float fx = x0 + (float)cx, fy = y0 + (float)cy;
            float w  = (cx? wx : 1.0f-wx)*(cy? wy : 1.0f-wy);
            if (fx>=0.f && fx<=(float)(WW-1) && fy>=0.f && fy<=(float)(HH-1)){
                int xi=(int)fx, yi=(int)fy;
                float gx=gridc(xi), gy=gridc(yi);
                float du0=duv[(yi*WW+xi)*2+0], du1=duv[(yi*WW+xi)*2+1];
                float vd=(fabsf(du0)<=1.0f && fabsf(du1)<=1.0f)?1.0f:0.0f;
                d0 += w*(du0-gx)*vd;  d1 += w*(du1-gy)*vd;
                c0 += w*gx;           c1 += w*gy;
                mk += w*vd;
            }
        }
    }
    g_coord[idx]=make_float2(c0,c1);
    g_delta[idx]=make_float2(d0,d1);
    float mb=(mk>0.5f)?1.0f:0.0f;
    g_mask[idx]=mb;
    int moff = NN*HW*2 + idx;
    if (moff < out_size) out[moff]=mb;
}

// ---------------- 2) gather control points ---------------------------------
__global__ void gather_src_kernel(){
    int t = blockIdx.x*blockDim.x + threadIdx.x;
    if (t >= NN*KC) return;
    int n=t/KC, k=t%KC;
    int ii=ctrl_i(k/KGC), jj=ctrl_i(k%KGC);
    int p = ii*WW + jj;
    g_src[t]=g_coord[n*HW+p];
    g_m[t]  =g_mask [n*HW+p];
}

// ---------------- 3) build augmented systems -------------------------------
__global__ void build_kernel(){
    int n = blockIdx.y;
    int e = blockIdx.x*blockDim.x + threadIdx.x;
    if (e >= NA*NC) return;
    int i=e/NC, j=e%NC;
    float v;
    if (j < KC){
        if (i < KC){
            float2 si=g_src[n*KC+i], sj=g_src[n*KC+j];
            float ddx=si.x-sj.x, ddy=si.y-sj.y;
            float r2=ddx*ddx+ddy*ddy;
            v = 0.5f*r2*logf(r2+EPSF);
            if (i==j) v += LAMBD + BIGV*(1.0f-g_m[n*KC+i]);
        } else {
            float2 sj=g_src[n*KC+j];
            v = (i==KC)?1.0f:((i==KC+1)?sj.x:sj.y);
        }
    } else if (j < NA){
        if (i < KC){
            float2 si=g_src[n*KC+i];
            v = (j==KC)?1.0f:((j==KC+1)?si.x:si.y);
        } else v = 0.0f;
    } else {
        if (i < KC){
            int ii=ctrl_i(i/KGC), jj=ctrl_i(i%KGC);
            v = (j==NA)? gridc(jj) : gridc(ii);
        } else v = 0.0f;
    }
    g_A[n][i*LD+j]=v;
}

// ---------------- 4) blocked LU (partial pivoting) + back-sub --------------
__global__ __launch_bounds__(1024,1) void lu_kernel(){
    const int n = blockIdx.x;
    float* __restrict__ A = g_A[n];
    int tid=threadIdx.x, lane=tid&31, wid=tid>>5;
    __shared__ float s_rv[32]; __shared__ int s_ri[32];
    __shared__ int   s_piv;    __shared__ float s_pinv;
    __shared__ __align__(16) float sU[8][408];
    __shared__ __align__(16) float sL[400*8];
    __shared__ float sx0[NA], sx1[NA];

    for (int kb=0; kb<NA; kb+=8){
        int Be = (NA-kb < 8) ? (NA-kb) : 8;
        // ---- panel factorization with partial pivoting
        for (int kk=0; kk<Be; kk++){
            int k = kb+kk;
            float bv=-1.0f; int bi=k;
            for (int i=k+tid;i<NA;i+=1024){
                float vv=fabsf(A[i*LD+k]);
                if (vv>bv){bv=vv;bi=i;}
            }
            #pragma unroll
            for (int o=16;o>0;o>>=1){
                float ov=__shfl_down_sync(0xffffffffu,bv,o);
                int   oi=__shfl_down_sync(0xffffffffu,bi,o);
                if (ov>bv){bv=ov;bi=oi;}
            }
            if (lane==0){ s_rv[wid]=bv; s_ri[wid]=bi; }
            __syncthreads();
            if (wid==0){
                bv=s_rv[lane]; bi=s_ri[lane];
                #pragma unroll
                for (int o=16;o>0;o>>=1){
                    float ov=__shfl_down_sync(0xffffffffu,bv,o);
                    int   oi=__shfl_down_sync(0xffffffffu,bi,o);
                    if (ov>bv){bv=ov;bi=oi;}
                }
                if (lane==0){ s_piv=bi; s_pinv=1.0f/A[bi*LD+k]; }
            }
            __syncthreads();
            int piv=s_piv; float pinv=s_pinv;
            if (piv!=k){
                for (int j=kb+tid;j<NC;j+=1024){
                    float t1=A[k*LD+j]; A[k*LD+j]=A[piv*LD+j]; A[piv*LD+j]=t1;
                }
            }
            __syncthreads();
            for (int i=k+1+tid;i<NA;i+=1024){
                float l=A[i*LD+k]*pinv;
                A[i*LD+k]=l;
                for (int j=k+1;j<kb+Be;j++)
                    A[i*LD+j] -= l*A[k*LD+j];
            }
            __syncthreads();
        }
        int c0c = kb+Be;
        int ncols = NC-c0c;
        int nrows = NA-c0c;
        // ---- U12 = L11^{-1} A12 (covers rhs columns too)
        for (int t=0;t<Be-1;t++){
            int nr = Be-1-t;
            int tot = nr*ncols;
            for (int e=tid;e<tot;e+=1024){
                int rr=e/ncols, j=c0c+e%ncols;
                int r=kb+t+1+rr;
                A[r*LD+j] -= A[r*LD+kb+t]*A[(kb+t)*LD+j];
            }
            __syncthreads();
        }
        // ---- trailing update A22 -= L21 * U12
        if (nrows > 0){
            int ncp=(ncols+3)&~3;
            for (int e=tid;e<8*ncp;e+=1024){
                int t=e/ncp, j=e%ncp;
                sU[t][j] = (t<Be && j<ncols) ? A[(kb+t)*LD+c0c+j] : 0.0f;
            }
            for (int e=tid;e<nrows*8;e+=1024){
                int r=e>>3, t=e&7;
                sL[e] = (t<Be) ? A[(c0c+r)*LD+kb+t] : 0.0f;
            }
            __syncthreads();
            int RT=(nrows+7)>>3, CT=ncp>>2;
            for (int tile=tid; tile<RT*CT; tile+=1024){
                int cj=(tile%CT)*4; int ri=(tile/CT)*8;
                float4 u0=*(const float4*)&sU[0][cj];
                float4 u1=*(const float4*)&sU[1][cj];
                float4 u2=*(const float4*)&sU[2][cj];
                float4 u3=*(const float4*)&sU[3][cj];
                float4 u4=*(const float4*)&sU[4][cj];
                float4 u5=*(const float4*)&sU[5][cj];
                float4 u6=*(const float4*)&sU[6][cj];
                float4 u7=*(const float4*)&sU[7][cj];
                #pragma unroll
                for (int r=0;r<8;r++){
                    int i=ri+r;
                    if (i>=nrows) break;
                    const float4 la=*(const float4*)&sL[i*8];
                    const float4 lb=*(const float4*)&sL[i*8+4];
                    float4* Cp=(float4*)&A[(c0c+i)*LD + c0c + cj];
                    float4 cc=*Cp;
                    cc.x=fmaf(-la.x,u0.x,cc.x); cc.x=fmaf(-la.y,u1.x,cc.x);
                    cc.x=fmaf(-la.z,u2.x,cc.x); cc.x=fmaf(-la.w,u3.x,cc.x);
                    cc.x=fmaf(-lb.x,u4.x,cc.x); cc.x=fmaf(-lb.y,u5.x,cc.x);
                    cc.x=fmaf(-lb.z,u6.x,cc.x); cc.x=fmaf(-lb.w,u7.x,cc.x);
                    cc.y=fmaf(-la.x,u0.y,cc.y); cc.y=fmaf(-la.y,u1.y,cc.y);
                    cc.y=fmaf(-la.z,u2.y,cc.y); cc.y=fmaf(-la.w,u3.y,cc.y);
                    cc.y=fmaf(-lb.x,u4.y,cc.y); cc.y=fmaf(-lb.y,u5.y,cc.y);
                    cc.y=fmaf(-lb.z,u6.y,cc.y); cc.y=fmaf(-lb.w,u7.y,cc.y);
                    cc.z=fmaf(-la.x,u0.z,cc.z); cc.z=fmaf(-la.y,u1.z,cc.z);
                    cc.z=fmaf(-la.z,u2.z,cc.z); cc.z=fmaf(-la.w,u3.z,cc.z);
                    cc.z=fmaf(-lb.x,u4.z,cc.z); cc.z=fmaf(-lb.y,u5.z,cc.z);
                    cc.z=fmaf(-lb.z,u6.z,cc.z); cc.z=fmaf(-lb.w,u7.z,cc.z);
                    cc.w=fmaf(-la.x,u0.w,cc.w); cc.w=fmaf(-la.y,u1.w,cc.w);
                    cc.w=fmaf(-la.z,u2.w,cc.w); cc.w=fmaf(-la.w,u3.w,cc.w);
                    cc.w=fmaf(-lb.x,u4.w,cc.w); cc.w=fmaf(-lb.y,u5.w,cc.w);
                    cc.w=fmaf(-lb.z,u6.w,cc.w); cc.w=fmaf(-lb.w,u7.w,cc.w);
                    *Cp=cc;
                }
            }
            __syncthreads();
        }
    }
    // ---- back substitution (warp 0)
    if (wid==0){
        for (int i=NA-1;i>=0;i--){
            float a0=0.f,a1=0.f;
            for (int j=i+1+lane;j<NA;j+=32){
                float aa=A[i*LD+j];
                a0 = fmaf(aa, sx0[j], a0);
                a1 = fmaf(aa, sx1[j], a1);
            }
            #pragma unroll
            for (int o=16;o>0;o>>=1){
                a0 += __shfl_down_sync(0xffffffffu,a0,o);
                a1 += __shfl_down_sync(0xffffffffu,a1,o);
            }
            if (lane==0){
                float dinv=1.0f/A[i*LD+i];
                sx0[i]=(A[i*LD+NA  ]-a0)*dinv;
                sx1[i]=(A[i*LD+NA+1]-a1)*dinv;
            }
            __syncwarp();
        }
    }
    __syncthreads();
    for (int k=tid;k<KC;k+=1024) g_wgt[n*KC+k]=make_float2(sx0[k],sx1[k]);
    if (tid<3) g_aff[n*3+tid]=make_float2(sx0[KC+tid],sx1[KC+tid]);
}

// ---------------- 5) TPS apply + Jacobian + final combine ------------------
__global__ __launch_bounds__(256) void apply_kernel(float* __restrict__ out, int out_size){
    int n = blockIdx.y;
    int p = blockIdx.x*256 + threadIdx.x;
    __shared__ float2 s_src[KC];
    __shared__ float2 s_wgt[KC];
    for (int k=threadIdx.x;k<KC;k+=256){
        s_src[k]=g_src[n*KC+k];
        s_wgt[k]=g_wgt[n*KC+k];
    }
    __syncthreads();
    int idx = n*HW + p;
    float2 q = g_coord[idx];
    float c00=0.f,c01=0.f,cx0=0.f,cx1=0.f,cy0=0.f,cy1=0.f;
    #pragma unroll 4
    for (int k=0;k<KC;k++){
        float2 s=s_src[k], wv=s_wgt[k];
        float ddx=q.x-s.x, ddy=q.y-s.y;
        float r20=fmaf(ddx,ddx,ddy*ddy);
        float r2x=fmaf(STEP, fmaf(2.0f,ddx,STEP), r20);
        float r2y=fmaf(STEP, fmaf(2.0f,ddy,STEP), r20);
        float U0=0.5f*r20*__logf(r20+EPSF);
        float Ux=0.5f*r2x*__logf(r2x+EPSF);
        float Uy=0.5f*r2y*__logf(r2y+EPSF);
        c00=fmaf(U0,wv.x,c00); c01=fmaf(U0,wv.y,c01);
        cx0=fmaf(Ux,wv.x,cx0); cx1=fmaf(Ux,wv.y,cx1);
        cy0=fmaf(Uy,wv.x,cy0); cy1=fmaf(Uy,wv.y,cy1);
    }
    float2 a0=g_aff[n*3+0], a1=g_aff[n*3+1], a2=g_aff[n*3+2];
    float qxx=q.x+STEP, qyy=q.y+STEP;
    c00 += a0.x + q.x*a1.x + q.y*a2.x;
    c01 += a0.y + q.x*a1.y + q.y*a2.y;
    cx0 += a0.x + qxx*a1.x + q.y*a2.x;
    cx1 += a0.y + qxx*a1.y + q.y*a2.y;
    cy0 += a0.x + q.x*a1.x + qyy*a2.x;
    cy1 += a0.y + q.x*a1.y + qyy*a2.y;
    const float inv = 1.0f/STEP;
    float a_=(cx0-c00)*inv, b_=(cx1-c01)*inv;
    float c_=(cy0-c00)*inv, d_=(cy1-c01)*inv;
    float2 df=g_delta[idx];
    float  m =g_mask [idx];
    float dn0 = a_*df.x + c_*df.y;
    float dn1 = b_*df.x + d_*df.y;
    int py=p/WW, px=p%WW;
    float gx=gridc(px), gy=gridc(py);
    float o0=(gx+dn0)*m - 2.0f*(1.0f-m);
    float o1=(gy+dn1)*m - 2.0f*(1.0f-m);
    if (idx*2+1 < out_size){
        out[idx*2+0]=o0;
        out[idx*2+1]=o1;
    }
}

// ---------------- launch ---------------------------------------------------
extern "C" void kernel_launch(void* const* d_in, const int* in_sizes, int n_in,
                              void* d_out, int out_size){
    const float* duv = (const float*)d_in[0];
    const float* uv  = (const float*)d_in[1];
    if (n_in >= 2 && in_sizes[0] != 2*HW){  // deform_uv should be 73728 elems
        const float* t=duv; duv=uv; uv=t;
    }
    float* out=(float*)d_out;

    warp_kernel<<<(NN*HW+255)/256,256>>>(duv, uv, out, out_size);
    gather_src_kernel<<<(NN*KC+255)/256,256>>>();
    dim3 gb((NA*NC+255)/256, NN);
    build_kernel<<<gb,256>>>();
    lu_kernel<<<NN,1024>>>();
    dim3 ga(HW/256, NN);
    apply_kernel<<<ga,256>>>(out, out_size);
}

// round 3
// speedup vs baseline: 1.5241x; 1.5241x over previous
#include <cuda_runtime.h>
#include <math.h>

#define HH 192
#define WW 192
#define NN 6
#define HW (HH*WW)
#define KGC 20
#define KC 400          /* control points */
#define NA 403          /* system size   */
#define NC 405          /* cols incl rhs */
#define LD 416          /* padded row stride (floats) */
#define LAMBD 100.0f
#define BIGV 100000000.0f
#define EPSF 1e-9f
#define STEP (2.0f/191.0f)

// ---------------- device scratch (no allocations allowed) ----------------
__device__ float2 g_coord[NN*HW];
__device__ float2 g_delta[NN*HW];
__device__ float  g_mask [NN*HW];
__device__ float2 g_src  [NN*KC];
__device__ float  g_m    [NN*KC];
__device__ __align__(16) float g_A[NN][NA*LD];
__device__ float2 g_wgt[NN*KC];
__device__ float2 g_aff[NN*3];

__device__ __forceinline__ float gridc(int i){ return -1.0f + (float)i*STEP; }
__device__ __forceinline__ int ctrl_i(int t){
    return (int)rintf((float)t * ((float)(HH-1)/(float)(KGC-1)));
}

// ---------------- 1) backward warp (delta/coord/mask on the fly) ----------
__global__ void warp_kernel(const float* __restrict__ duv,
                            const float* __restrict__ uv,
                            float* __restrict__ out, int out_size){
    int idx = blockIdx.x*blockDim.x + threadIdx.x;
    if (idx >= NN*HW) return;
    float u = uv[idx*2+0], v = uv[idx*2+1];
    float x = (u + 1.0f)*0.5f*(float)(WW-1);
    float y = (v + 1.0f)*0.5f*(float)(HH-1);
    float x0 = floorf(x), y0 = floorf(y);
    float wx = x - x0, wy = y - y0;
    float d0=0.f,d1=0.f,c0=0.f,c1=0.f,mk=0.f;
    #pragma unroll
    for (int cy=0; cy<2; cy++){
        #pragma unroll
        for (int cx=0; cx<2; cx++){
            float fx = x0 + (float)cx, fy = y0 + (float)cy;
            float w  = (cx? wx : 1.0f-wx)*(cy? wy : 1.0f-wy);
            if (fx>=0.f && fx<=(float)(WW-1) && fy>=0.f && fy<=(float)(HH-1)){
                int xi=(int)fx, yi=(int)fy;
                float gx=gridc(xi), gy=gridc(yi);
                float du0=duv[(yi*WW+xi)*2+0], du1=duv[(yi*WW+xi)*2+1];
                float vd=(fabsf(du0)<=1.0f && fabsf(du1)<=1.0f)?1.0f:0.0f;
                d0 += w*(du0-gx)*vd;  d1 += w*(du1-gy)*vd;
                c0 += w*gx;           c1 += w*gy;
                mk += w*vd;
            }
        }
    }
    g_coord[idx]=make_float2(c0,c1);
    g_delta[idx]=make_float2(d0,d1);
    float mb=(mk>0.5f)?1.0f:0.0f;
    g_mask[idx]=mb;
    int moff = NN*HW*2 + idx;
    if (moff < out_size) out[moff]=mb;
}

// ---------------- 2) gather control points ---------------------------------
__global__ void gather_src_kernel(){
    int t = blockIdx.x*blockDim.x + threadIdx.x;
    if (t >= NN*KC) return;
    int n=t/KC, k=t%KC;
    int ii=ctrl_i(k/KGC), jj=ctrl_i(k%KGC);
    int p = ii*WW + jj;
    g_src[t]=g_coord[n*HW+p];
    g_m[t]  =g_mask [n*HW+p];
}

// ---------------- 3) build augmented systems -------------------------------
__global__ void build_kernel(){
    int n = blockIdx.y;
    int e = blockIdx.x*blockDim.x + threadIdx.x;
    if (e >= NA*NC) return;
    int i=e/NC, j=e%NC;
    float v;
    if (j < KC){
        if (i < KC){
            float2 si=g_src[n*KC+i], sj=g_src[n*KC+j];
            float ddx=si.x-sj.x, ddy=si.y-sj.y;
            float r2=ddx*ddx+ddy*ddy;
            v = 0.5f*r2*logf(r2+EPSF);
            if (i==j) v += LAMBD + BIGV*(1.0f-g_m[n*KC+i]);
        } else {
            float2 sj=g_src[n*KC+j];
            v = (i==KC)?1.0f:((i==KC+1)?sj.x:sj.y);
        }
    } else if (j < NA){
        if (i < KC){
            float2 si=g_src[n*KC+i];
            v = (j==KC)?1.0f:((j==KC+1)?si.x:si.y);
        } else v = 0.0f;
    } else {
        if (i < KC){
            int ii=ctrl_i(i/KGC), jj=ctrl_i(i%KGC);
            v = (j==NA)? gridc(jj) : gridc(ii);
        } else v = 0.0f;
    }
    g_A[n][i*LD+j]=v;
}

// ---------------- 4) blocked LU: SMEM panel factor + parallel U12 ----------
__global__ __launch_bounds__(512,1) void lu_kernel(){
    const int n = blockIdx.x;
    float* __restrict__ A = g_A[n];
    const int tid=threadIdx.x, lane=tid&31, wid=tid>>5;
    __shared__ float SP[NA][9];                 // panel (stride 9: conflict-free)
    __shared__ __align__(16) float sU[8][400];  // staged U12 strip
    __shared__ float s_rv[16]; __shared__ int s_ri[16];
    __shared__ int   s_piva[8]; __shared__ float s_pinv;
    __shared__ float sx0[NA], sx1[NA];

    for (int kb=0; kb<NA; kb+=8){
        const int Be   = (NA-kb < 8) ? (NA-kb) : 8;
        const int c0c  = kb+Be;
        const int ncols= NC-c0c;
        const int nrows= NA-c0c;

        // ---- load panel (cols kb..kb+7, rows kb..NA-1) into SMEM
        for (int i=kb+tid; i<NA; i+=512){
            const float4* pr=(const float4*)&A[i*LD+kb];
            float4 p0=pr[0], p1=pr[1];
            SP[i][0]=p0.x; SP[i][1]=p0.y; SP[i][2]=p0.z; SP[i][3]=p0.w;
            SP[i][4]=p1.x; SP[i][5]=p1.y; SP[i][6]=p1.z; SP[i][7]=p1.w;
        }
        __syncthreads();

        // ---- factor panel in SMEM with partial pivoting
        for (int kk=0; kk<Be; kk++){
            const int k = kb+kk;
            float bv=-1.0f; int bi=k;
            for (int i=k+tid; i<NA; i+=512){
                float vv=fabsf(SP[i][kk]);
                if (vv>bv){bv=vv;bi=i;}
            }
            #pragma unroll
            for (int o=16;o>0;o>>=1){
                float ov=__shfl_down_sync(0xffffffffu,bv,o);
                int   oi=__shfl_down_sync(0xffffffffu,bi,o);
                if (ov>bv){bv=ov;bi=oi;}
            }
            if (lane==0){ s_rv[wid]=bv; s_ri[wid]=bi; }
            __syncthreads();
            if (wid==0){
                bv = (lane<16)? s_rv[lane] : -2.0f;
                bi = (lane<16)? s_ri[lane] : k;
                #pragma unroll
                for (int o=8;o>0;o>>=1){
                    float ov=__shfl_down_sync(0xffffffffu,bv,o);
                    int   oi=__shfl_down_sync(0xffffffffu,bi,o);
                    if (ov>bv){bv=ov;bi=oi;}
                }
                if (lane==0){ s_piva[kk]=bi; s_pinv=1.0f/SP[bi][kk]; }
            }
            __syncthreads();
            const int piv=s_piva[kk]; const float pinv=s_pinv;
            if (piv!=k){
                if (tid<8){ float t1=SP[k][tid]; SP[k][tid]=SP[piv][tid]; SP[piv][tid]=t1; }
                __syncthreads();
            }
            for (int i=k+1+tid; i<NA; i+=512){
                float l=SP[i][kk]*pinv;
                SP[i][kk]=l;
                #pragma unroll
                for (int j=1;j<8;j++){
                    int jj=kk+j;
                    if (jj<Be) SP[i][jj]=fmaf(-l,SP[k][jj],SP[i][jj]);
                }
            }
            __syncthreads();
        }

        // ---- apply deferred row swaps to global, only cols >= c0c (incl rhs).
        //      L-columns left of the panel are never read again -> skip them.
        for (int kk=0; kk<Be; kk++){
            const int k=kb+kk, piv=s_piva[kk];
            if (piv!=k){
                for (int j=c0c+tid; j<NC; j+=512){
                    float t1=A[k*LD+j]; A[k*LD+j]=A[piv*LD+j]; A[piv*LD+j]=t1;
                }
                __syncthreads();
            }
        }

        // ---- write factored panel back (only valid Be cols)
        if (Be==8){
            for (int i=kb+tid; i<NA; i+=512){
                float4 p0=make_float4(SP[i][0],SP[i][1],SP[i][2],SP[i][3]);
                float4 p1=make_float4(SP[i][4],SP[i][5],SP[i][6],SP[i][7]);
                float4* pr=(float4*)&A[i*LD+kb];
                pr[0]=p0; pr[1]=p1;
            }
        } else {
            for (int e=tid; e<(NA-kb)*Be; e+=512){
                int i=kb+e/Be, c=e%Be;
                A[i*LD+kb+c]=SP[i][c];
            }
        }

        // ---- U12 = L11^{-1} A12 in ONE parallel pass; stage into sU
        const int ncp=(ncols+3)&~3;
        for (int j=c0c+tid; j<NC; j+=512){
            float a[8];
            #pragma unroll
            for (int t=0;t<8;t++) a[t] = (t<Be)? A[(kb+t)*LD+j] : 0.0f;
            #pragma unroll
            for (int t=1;t<8;t++){
                if (t<Be){
                    #pragma unroll
                    for (int s=0;s<7;s++)
                        if (s<t) a[t]=fmaf(-SP[kb+t][s],a[s],a[t]);
                }
            }
            #pragma unroll
            for (int t=0;t<8;t++) if (t<Be){ A[(kb+t)*LD+j]=a[t]; sU[t][j-c0c]=a[t]; }
        }
        for (int j=ncols+tid; j<ncp; j+=512){
            #pragma unroll
            for (int t=0;t<8;t++) sU[t][j]=0.0f;
        }
        __syncthreads();

        // ---- trailing update A22 -= L21 * U12 (L21 lives in SP)
        if (nrows>0 && Be==8){
            const int RT=(nrows+7)>>3, CT=ncp>>2;
            for (int tile=tid; tile<RT*CT; tile+=512){
                const int cj=(tile%CT)*4, ri=(tile/CT)*8;
                float4 u0=*(const float4*)&sU[0][cj];
                float4 u1=*(const float4*)&sU[1][cj];
                float4 u2=*(const float4*)&sU[2][cj];
                float4 u3=*(const float4*)&sU[3][cj];
                float4 u4=*(const float4*)&sU[4][cj];
                float4 u5=*(const float4*)&sU[5][cj];
                float4 u6=*(const float4*)&sU[6][cj];
                float4 u7=*(const float4*)&sU[7][cj];
                #pragma unroll
                for (int r=0;r<8;r++){
                    const int i=ri+r;
                    if (i>=nrows) break;
                    const float* Lr=SP[c0c+i];
                    const float l0=Lr[0],l1=Lr[1],l2=Lr[2],l3=Lr[3];
                    const float l4=Lr[4],l5=Lr[5],l6=Lr[6],l7=Lr[7];
                    float4* Cp=(float4*)&A[(c0c+i)*LD + c0c + cj];
                    float4 cc=*Cp;
                    cc.x=fmaf(-l0,u0.x,cc.x); cc.x=fmaf(-l1,u1.x,cc.x);
                    cc.x=fmaf(-l2,u2.x,cc.x); cc.x=fmaf(-l3,u3.x,cc.x);
                    cc.x=fmaf(-l4,u4.x,cc.x); cc.x=fmaf(-l5,u5.x,cc.x);
                    cc.x=fmaf(-l6,u6.x,cc.x); cc.x=fmaf(-l7,u7.x,cc.x);
                    cc.y=fmaf(-l0,u0.y,cc.y); cc.y=fmaf(-l1,u1.y,cc.y);
                    cc.y=fmaf(-l2,u2.y,cc.y); cc.y=fmaf(-l3,u3.y,cc.y);
                    cc.y=fmaf(-l4,u4.y,cc.y); cc.y=fmaf(-l5,u5.y,cc.y);
                    cc.y=fmaf(-l6,u6.y,cc.y); cc.y=fmaf(-l7,u7.y,cc.y);
                    cc.z=fmaf(-l0,u0.z,cc.z); cc.z=fmaf(-l1,u1.z,cc.z);
                    cc.z=fmaf(-l2,u2.z,cc.z); cc.z=fmaf(-l3,u3.z,cc.z);
                    cc.z=fmaf(-l4,u4.z,cc.z); cc.z=fmaf(-l5,u5.z,cc.z);
                    cc.z=fmaf(-l6,u6.z,cc.z); cc.z=fmaf(-l7,u7.z,cc.z);
                    cc.w=fmaf(-l0,u0.w,cc.w); cc.w=fmaf(-l1,u1.w,cc.w);
                    cc.w=fmaf(-l2,u2.w,cc.w); cc.w=fmaf(-l3,u3.w,cc.w);
                    cc.w=fmaf(-l4,u4.w,cc.w); cc.w=fmaf(-l5,u5.w,cc.w);
                    cc.w=fmaf(-l6,u6.w,cc.w); cc.w=fmaf(-l7,u7.w,cc.w);
                    *Cp=cc;
                }
            }
        }
        __syncthreads();
    }

    // ---- back substitution (warp 0)
    if (wid==0){
        for (int i=NA-1;i>=0;i--){
            float a0=0.f,a1=0.f;
            for (int j=i+1+lane;j<NA;j+=32){
                float aa=A[i*LD+j];
                a0 = fmaf(aa, sx0[j], a0);
                a1 = fmaf(aa, sx1[j], a1);
            }
            #pragma unroll
            for (int o=16;o>0;o>>=1){
                a0 += __shfl_down_sync(0xffffffffu,a0,o);
                a1 += __shfl_down_sync(0xffffffffu,a1,o);
            }
            if (lane==0){
                float dinv=1.0f/A[i*LD+i];
                sx0[i]=(A[i*LD+NA  ]-a0)*dinv;
                sx1[i]=(A[i*LD+NA+1]-a1)*dinv;
            }
            __syncwarp();
        }
    }
    __syncthreads();
    for (int k=tid;k<KC;k+=512) g_wgt[n*KC+k]=make_float2(sx0[k],sx1[k]);
    if (tid<3) g_aff[n*3+tid]=make_float2(sx0[KC+tid],sx1[KC+tid]);
}

// ---------------- 5) TPS apply + Jacobian + final combine ------------------
__global__ __launch_bounds__(256) void apply_kernel(float* __restrict__ out, int out_size){
    int n = blockIdx.y;
    int p = blockIdx.x*256 + threadIdx.x;
    __shared__ float2 s_src[KC];
    __shared__ float2 s_wgt[KC];
    for (int k=threadIdx.x;k<KC;k+=256){
        s_src[k]=g_src[n*KC+k];
        s_wgt[k]=g_wgt[n*KC+k];
    }
    __syncthreads();
    int idx = n*HW + p;
    float2 q = g_coord[idx];
    float c00=0.f,c01=0.f,cx0=0.f,cx1=0.f,cy0=0.f,cy1=0.f;
    #pragma unroll 4
    for (int k=0;k<KC;k++){
        float2 s=s_src[k], wv=s_wgt[k];
        float ddx=q.x-s.x, ddy=q.y-s.y;
        float r20=fmaf(ddx,ddx,ddy*ddy);
        float r2x=fmaf(STEP, fmaf(2.0f,ddx,STEP), r20);
        float r2y=fmaf(STEP, fmaf(2.0f,ddy,STEP), r20);
        float U0=0.5f*r20*__logf(r20+EPSF);
        float Ux=0.5f*r2x*__logf(r2x+EPSF);
        float Uy=0.5f*r2y*__logf(r2y+EPSF);
        c00=fmaf(U0,wv.x,c00); c01=fmaf(U0,wv.y,c01);
        cx0=fmaf(Ux,wv.x,cx0); cx1=fmaf(Ux,wv.y,cx1);
        cy0=fmaf(Uy,wv.x,cy0); cy1=fmaf(Uy,wv.y,cy1);
    }
    float2 a0=g_aff[n*3+0], a1=g_aff[n*3+1], a2=g_aff[n*3+2];
    float qxx=q.x+STEP, qyy=q.y+STEP;
    c00 += a0.x + q.x*a1.x + q.y*a2.x;
    c01 += a0.y + q.x*a1.y + q.y*a2.y;
    cx0 += a0.x + qxx*a1.x + q.y*a2.x;
    cx1 += a0.y + qxx*a1.y + q.y*a2.y;
    cy0 += a0.x + q.x*a1.x + qyy*a2.x;
    cy1 += a0.y + q.x*a1.y + qyy*a2.y;
    const float inv = 1.0f/STEP;
    float a_=(cx0-c00)*inv, b_=(cx1-c01)*inv;
    float c_=(cy0-c00)*inv, d_=(cy1-c01)*inv;
    float2 df=g_delta[idx];
    float  m =g_mask [idx];
    float dn0 = a_*df.x + c_*df.y;
    float dn1 = b_*df.x + d_*df.y;
    int py=p/WW, px=p%WW;
    float gx=gridc(px), gy=gridc(py);
    float o0=(gx+dn0)*m - 2.0f*(1.0f-m);
    float o1=(gy+dn1)*m - 2.0f*(1.0f-m);
    if (idx*2+1 < out_size){
        out[idx*2+0]=o0;
        out[idx*2+1]=o1;
    }
}

// ---------------- launch ---------------------------------------------------
extern "C" void kernel_launch(void* const* d_in, const int* in_sizes, int n_in,
                              void* d_out, int out_size){
    const float* duv = (const float*)d_in[0];
    const float* uv  = (const float*)d_in[1];
    if (n_in >= 2 && in_sizes[0] != 2*HW){
        const float* t=duv; duv=uv; uv=t;
    }
    float* out=(float*)d_out;

    warp_kernel<<<(NN*HW+255)/256,256>>>(duv, uv, out, out_size);
    gather_src_kernel<<<(NN*KC+255)/256,256>>>();
    dim3 gb((NA*NC+255)/256, NN);
    build_kernel<<<gb,256>>>();
    lu_kernel<<<NN,512>>>();
    dim3 ga(HW/256, NN);
    apply_kernel<<<ga,256>>>(out, out_size);
}

// round 8
// speedup vs baseline: 1.7989x; 1.1803x over previous
#include <cuda_runtime.h>
#include <math.h>

#define HH 192
#define WW 192
#define NN 6
#define HW (HH*WW)
#define KGC 20
#define KC 400          /* control points */
#define NA 403          /* system size   */
#define NC 405          /* cols incl rhs */
#define LD 416          /* padded row stride (floats) */
#define LAMBD 100.0f
#define BIGV 100000000.0f
#define EPSF 1e-9f
#define STEP (2.0f/191.0f)

// ---------------- device scratch (no allocations allowed) ----------------
__device__ float2 g_coord[NN*HW];
__device__ float2 g_delta[NN*HW];
__device__ float  g_mask [NN*HW];
__device__ float2 g_src  [NN*KC];
__device__ float  g_m    [NN*KC];
__device__ __align__(16) float g_A[NN][NA*LD];
__device__ float2 g_wgt[NN*KC];
__device__ float2 g_aff[NN*3];

__device__ __forceinline__ float gridc(int i){ return -1.0f + (float)i*STEP; }
__device__ __forceinline__ int ctrl_i(int t){
    return (int)rintf((float)t * ((float)(HH-1)/(float)(KGC-1)));
}

// ---------------- 1) backward warp (delta/coord/mask on the fly) ----------
__global__ void warp_kernel(const float* __restrict__ duv,
                            const float* __restrict__ uv,
                            float* __restrict__ out, int out_size){
    int idx = blockIdx.x*blockDim.x + threadIdx.x;
    if (idx >= NN*HW) return;
    float u = uv[idx*2+0], v = uv[idx*2+1];
    float x = (u + 1.0f)*0.5f*(float)(WW-1);
    float y = (v + 1.0f)*0.5f*(float)(HH-1);
    float x0 = floorf(x), y0 = floorf(y);
    float wx = x - x0, wy = y - y0;
    float d0=0.f,d1=0.f,c0=0.f,c1=0.f,mk=0.f;
    #pragma unroll
    for (int cy=0; cy<2; cy++){
        #pragma unroll
        for (int cx=0; cx<2; cx++){
            float fx = x0 + (float)cx, fy = y0 + (float)cy;
            float w  = (cx? wx : 1.0f-wx)*(cy? wy : 1.0f-wy);
            if (fx>=0.f && fx<=(float)(WW-1) && fy>=0.f && fy<=(float)(HH-1)){
                int xi=(int)fx, yi=(int)fy;
                float gx=gridc(xi), gy=gridc(yi);
                float du0=duv[(yi*WW+xi)*2+0], du1=duv[(yi*WW+xi)*2+1];
                float vd=(fabsf(du0)<=1.0f && fabsf(du1)<=1.0f)?1.0f:0.0f;
                d0 += w*(du0-gx)*vd;  d1 += w*(du1-gy)*vd;
                c0 += w*gx;           c1 += w*gy;
                mk += w*vd;
            }
        }
    }
    g_coord[idx]=make_float2(c0,c1);
    g_delta[idx]=make_float2(d0,d1);
    float mb=(mk>0.5f)?1.0f:0.0f;
    g_mask[idx]=mb;
    int moff = NN*HW*2 + idx;
    if (moff < out_size) out[moff]=mb;
}

// ---------------- 2) gather control points ---------------------------------
__global__ void gather_src_kernel(){
    int t = blockIdx.x*blockDim.x + threadIdx.x;
    if (t >= NN*KC) return;
    int n=t/KC, k=t%KC;
    int ii=ctrl_i(k/KGC), jj=ctrl_i(k%KGC);
    int p = ii*WW + jj;
    g_src[t]=g_coord[n*HW+p];
    g_m[t]  =g_mask [n*HW+p];
}

// ---------------- 3) build augmented systems -------------------------------
__global__ void build_kernel(){
    int n = blockIdx.y;
    int e = blockIdx.x*blockDim.x + threadIdx.x;
    if (e >= NA*NC) return;
    int i=e/NC, j=e%NC;
    float v;
    if (j < KC){
        if (i < KC){
            float2 si=g_src[n*KC+i], sj=g_src[n*KC+j];
            float ddx=si.x-sj.x, ddy=si.y-sj.y;
            float r2=ddx*ddx+ddy*ddy;
            v = 0.5f*r2*logf(r2+EPSF);
            if (i==j) v += LAMBD + BIGV*(1.0f-g_m[n*KC+i]);
        } else {
            float2 sj=g_src[n*KC+j];
            v = (i==KC)?1.0f:((i==KC+1)?sj.x:sj.y);
        }
    } else if (j < NA){
        if (i < KC){
            float2 si=g_src[n*KC+i];
            v = (j==KC)?1.0f:((j==KC+1)?si.x:si.y);
        } else v = 0.0f;
    } else {
        if (i < KC){
            int ii=ctrl_i(i/KGC), jj=ctrl_i(i%KGC);
            v = (j==NA)? gridc(jj) : gridc(ii);
        } else v = 0.0f;
    }
    g_A[n][i*LD+j]=v;
}

// ------- 4) blocked LU, NO PIVOTING on rows 0..399 (diag >= lambda=100) ----
//            final 3x3 bordered Schur block solved with full pivoting.
__global__ __launch_bounds__(512,1) void lu_kernel(){
    const int n = blockIdx.x;
    float* __restrict__ A = g_A[n];
    const int tid=threadIdx.x, lane=tid&31, wid=tid>>5;
    __shared__ float SP[NA][9];                 // panel (stride 9: conflict-free)
    __shared__ __align__(16) float sU[8][400];  // staged U12 strip
    __shared__ float s_invd[8];
    __shared__ float sx0[NA], sx1[NA];

    for (int kb=0; kb<400; kb+=8){
        const int c0c  = kb+8;
        const int ncols= NC-c0c;
        const int nrows= NA-c0c;

        // ---- load panel (cols kb..kb+7, rows kb..NA-1) into SMEM
        for (int i=kb+tid; i<NA; i+=512){
            const float4* pr=(const float4*)&A[i*LD+kb];
            float4 p0=pr[0], p1=pr[1];
            SP[i][0]=p0.x; SP[i][1]=p0.y; SP[i][2]=p0.z; SP[i][3]=p0.w;
            SP[i][4]=p1.x; SP[i][5]=p1.y; SP[i][6]=p1.z; SP[i][7]=p1.w;
        }
        __syncthreads();

        // ---- factor 8x8 diagonal block in registers (warp 0, lanes 0-7)
        if (wid==0 && lane<8){
            float d[8];
            #pragma unroll
            for (int c=0;c<8;c++) d[c]=SP[kb+lane][c];
            #pragma unroll
            for (int k=0;k<8;k++){
                float ukk = __shfl_sync(0xFFu, d[k], k);
                float inv = 1.0f/ukk;
                if (lane==k) s_invd[k]=inv;
                float l = d[k]*inv;
                bool below = lane>k;
                if (below) d[k]=l;
                #pragma unroll
                for (int j=0;j<8;j++){
                    if (j>k){
                        float ukj = __shfl_sync(0xFFu, d[j], k);
                        if (below) d[j]=fmaf(-l,ukj,d[j]);
                    }
                }
            }
            #pragma unroll
            for (int c=0;c<8;c++) SP[kb+lane][c]=d[c];
        }
        __syncthreads();

        // cache diag inverses
        const float i0=s_invd[0],i1=s_invd[1],i2=s_invd[2],i3=s_invd[3];
        const float i4=s_invd[4],i5=s_invd[5],i6=s_invd[6],i7=s_invd[7];

        // ---- L21 rows, fully parallel: solve l * U11 = a per row
        for (int i=c0c+tid; i<NA; i+=512){
            float a0=SP[i][0],a1=SP[i][1],a2=SP[i][2],a3=SP[i][3];
            float a4=SP[i][4],a5=SP[i][5],a6=SP[i][6],a7=SP[i][7];
            float l0=a0*i0;
            float l1=(a1-l0*SP[kb+0][1])*i1;
            float l2=(a2-l0*SP[kb+0][2]-l1*SP[kb+1][2])*i2;
            float l3=(a3-l0*SP[kb+0][3]-l1*SP[kb+1][3]-l2*SP[kb+2][3])*i3;
            float l4=(a4-l0*SP[kb+0][4]-l1*SP[kb+1][4]-l2*SP[kb+2][4]-l3*SP[kb+3][4])*i4;
            float l5=(a5-l0*SP[kb+0][5]-l1*SP[kb+1][5]-l2*SP[kb+2][5]-l3*SP[kb+3][5]-l4*SP[kb+4][5])*i5;
            float l6=(a6-l0*SP[kb+0][6]-l1*SP[kb+1][6]-l2*SP[kb+2][6]-l3*SP[kb+3][6]-l4*SP[kb+4][6]-l5*SP[kb+5][6])*i6;
            float l7=(a7-l0*SP[kb+0][7]-l1*SP[kb+1][7]-l2*SP[kb+2][7]-l3*SP[kb+3][7]-l4*SP[kb+4][7]-l5*SP[kb+5][7]-l6*SP[kb+6][7])*i7;
            SP[i][0]=l0; SP[i][1]=l1; SP[i][2]=l2; SP[i][3]=l3;
            SP[i][4]=l4; SP[i][5]=l5; SP[i][6]=l6; SP[i][7]=l7;
            float4* pr=(float4*)&A[i*LD+kb];
            pr[0]=make_float4(l0,l1,l2,l3);
            pr[1]=make_float4(l4,l5,l6,l7);
        }
        // ---- panel top rows writeback (L11\U11)
        if (tid<8){
            float4* pr=(float4*)&A[(kb+tid)*LD+kb];
            pr[0]=make_float4(SP[kb+tid][0],SP[kb+tid][1],SP[kb+tid][2],SP[kb+tid][3]);
            pr[1]=make_float4(SP[kb+tid][4],SP[kb+tid][5],SP[kb+tid][6],SP[kb+tid][7]);
        }
        // ---- U12 = L11^{-1} A12, one parallel pass; stage into sU
        const int ncp=(ncols+3)&~3;
        for (int j=c0c+tid; j<NC; j+=512){
            float a[8];
            #pragma unroll
            for (int t=0;t<8;t++) a[t]=A[(kb+t)*LD+j];
            #pragma unroll
            for (int t=1;t<8;t++){
                #pragma unroll
                for (int s=0;s<7;s++)
                    if (s<t) a[t]=fmaf(-SP[kb+t][s],a[s],a[t]);
            }
            #pragma unroll
            for (int t=0;t<8;t++){ A[(kb+t)*LD+j]=a[t]; sU[t][j-c0c]=a[t]; }
        }
        for (int j=ncols+tid; j<ncp; j+=512){
            #pragma unroll
            for (int t=0;t<8;t++) sU[t][j]=0.0f;
        }
        __syncthreads();

        // ---- trailing update A22 -= L21 * U12 (L21 in SP, U12 in sU)
        {
            const int RT=(nrows+7)>>3, CT=ncp>>2;
            for (int tile=tid; tile<RT*CT; tile+=512){
                const int cj=(tile%CT)*4, ri=(tile/CT)*8;
                float4 u0=*(const float4*)&sU[0][cj];
                float4 u1=*(const float4*)&sU[1][cj];
                float4 u2=*(const float4*)&sU[2][cj];
                float4 u3=*(const float4*)&sU[3][cj];
                float4 u4=*(const float4*)&sU[4][cj];
                float4 u5=*(const float4*)&sU[5][cj];
                float4 u6=*(const float4*)&sU[6][cj];
                float4 u7=*(const float4*)&sU[7][cj];
                #pragma unroll
                for (int r=0;r<8;r++){
                    const int i=ri+r;
                    if (i>=nrows) break;
                    const float* Lr=SP[c0c+i];
                    const float l0=Lr[0],l1=Lr[1],l2=Lr[2],l3=Lr[3];
                    const float l4=Lr[4],l5=Lr[5],l6=Lr[6],l7=Lr[7];
                    float4* Cp=(float4*)&A[(c0c+i)*LD + c0c + cj];
                    float4 cc=*Cp;
                    cc.x=fmaf(-l0,u0.x,cc.x); cc.x=fmaf(-l1,u1.x,cc.x);
                    cc.x=fmaf(-l2,u2.x,cc.x); cc.x=fmaf(-l3,u3.x,cc.x);
                    cc.x=fmaf(-l4,u4.x,cc.x); cc.x=fmaf(-l5,u5.x,cc.x);
                    cc.x=fmaf(-l6,u6.x,cc.x); cc.x=fmaf(-l7,u7.x,cc.x);
                    cc.y=fmaf(-l0,u0.y,cc.y); cc.y=fmaf(-l1,u1.y,cc.y);
                    cc.y=fmaf(-l2,u2.y,cc.y); cc.y=fmaf(-l3,u3.y,cc.y);
                    cc.y=fmaf(-l4,u4.y,cc.y); cc.y=fmaf(-l5,u5.y,cc.y);
                    cc.y=fmaf(-l6,u6.y,cc.y); cc.y=fmaf(-l7,u7.y,cc.y);
                    cc.z=fmaf(-l0,u0.z,cc.z); cc.z=fmaf(-l1,u1.z,cc.z);
                    cc.z=fmaf(-l2,u2.z,cc.z); cc.z=fmaf(-l3,u3.z,cc.z);
                    cc.z=fmaf(-l4,u4.z,cc.z); cc.z=fmaf(-l5,u5.z,cc.z);
                    cc.z=fmaf(-l6,u6.z,cc.z); cc.z=fmaf(-l7,u7.z,cc.z);
                    cc.w=fmaf(-l0,u0.w,cc.w); cc.w=fmaf(-l1,u1.w,cc.w);
                    cc.w=fmaf(-l2,u2.w,cc.w); cc.w=fmaf(-l3,u3.w,cc.w);
                    cc.w=fmaf(-l4,u4.w,cc.w); cc.w=fmaf(-l5,u5.w,cc.w);
                    cc.w=fmaf(-l6,u6.w,cc.w); cc.w=fmaf(-l7,u7.w,cc.w);
                    *Cp=cc;
                }
            }
        }
        __syncthreads();
    }

    // ---- final 3x5 bordered block: full-pivot Gauss-Jordan + back-sub
    if (wid==0){
        if (lane==0){
            float M[3][5];
            #pragma unroll
            for (int r=0;r<3;r++)
                #pragma unroll
                for (int c=0;c<5;c++)
                    M[r][c]=A[(400+r)*LD+400+c];
            #pragma unroll
            for (int k=0;k<3;k++){
                int p=k;
                float bv=fabsf(M[k][k]);
                #pragma unroll
                for (int r=0;r<3;r++)
                    if (r>k && fabsf(M[r][k])>bv){bv=fabsf(M[r][k]);p=r;}
                if (p!=k){
                    #pragma unroll
                    for (int c=0;c<5;c++){float t1=M[k][c];M[k][c]=M[p][c];M[p][c]=t1;}
                }
                float inv=1.0f/M[k][k];
                #pragma unroll
                for (int c=0;c<5;c++) M[k][c]*=inv;
                #pragma unroll
                for (int r=0;r<3;r++){
                    if (r!=k){
                        float f=M[r][k];
                        #pragma unroll
                        for (int c=0;c<5;c++) M[r][c]=fmaf(-f,M[k][c],M[r][c]);
                    }
                }
            }
            #pragma unroll
            for (int r=0;r<3;r++){ sx0[400+r]=M[r][3]; sx1[400+r]=M[r][4]; }
        }
        __syncwarp();
        for (int i=399;i>=0;i--){
            float a0=0.f,a1=0.f;
            for (int j=i+1+lane;j<NA;j+=32){
                float aa=A[i*LD+j];
                a0 = fmaf(aa, sx0[j], a0);
                a1 = fmaf(aa, sx1[j], a1);
            }
            #pragma unroll
            for (int o=16;o>0;o>>=1){
                a0 += __shfl_down_sync(0xffffffffu,a0,o);
                a1 += __shfl_down_sync(0xffffffffu,a1,o);
            }
            if (lane==0){
                float dinv=1.0f/A[i*LD+i];
                sx0[i]=(A[i*LD+NA  ]-a0)*dinv;
                sx1[i]=(A[i*LD+NA+1]-a1)*dinv;
            }
            __syncwarp();
        }
    }
    __syncthreads();
    for (int k=tid;k<KC;k+=512) g_wgt[n*KC+k]=make_float2(sx0[k],sx1[k]);
    if (tid<3) g_aff[n*3+tid]=make_float2(sx0[KC+tid],sx1[KC+tid]);
}

// ---------------- 5) TPS apply + Jacobian + final combine ------------------
__global__ __launch_bounds__(256) void apply_kernel(float* __restrict__ out, int out_size){
    int n = blockIdx.y;
    int p = blockIdx.x*256 + threadIdx.x;
    __shared__ float2 s_src[KC];
    __shared__ float2 s_wgt[KC];
    for (int k=threadIdx.x;k<KC;k+=256){
        s_src[k]=g_src[n*KC+k];
        s_wgt[k]=g_wgt[n*KC+k];
    }
    __syncthreads();
    int idx = n*HW + p;
    float2 q = g_coord[idx];
    float c00=0.f,c01=0.f,cx0=0.f,cx1=0.f,cy0=0.f,cy1=0.f;
    #pragma unroll 4
    for (int k=0;k<KC;k++){
        float2 s=s_src[k], wv=s_wgt[k];
        float ddx=q.x-s.x, ddy=q.y-s.y;
        float r20=fmaf(ddx,ddx,ddy*ddy);
        float r2x=fmaf(STEP, fmaf(2.0f,ddx,STEP), r20);
        float r2y=fmaf(STEP, fmaf(2.0f,ddy,STEP), r20);
        float U0=0.5f*r20*__logf(r20+EPSF);
        float Ux=0.5f*r2x*__logf(r2x+EPSF);
        float Uy=0.5f*r2y*__logf(r2y+EPSF);
        c00=fmaf(U0,wv.x,c00); c01=fmaf(U0,wv.y,c01);
        cx0=fmaf(Ux,wv.x,cx0); cx1=fmaf(Ux,wv.y,cx1);
        cy0=fmaf(Uy,wv.x,cy0); cy1=fmaf(Uy,wv.y,cy1);
    }
    float2 a0=g_aff[n*3+0], a1=g_aff[n*3+1], a2=g_aff[n*3+2];
    float qxx=q.x+STEP, qyy=q.y+STEP;
    c00 += a0.x + q.x*a1.x + q.y*a2.x;
    c01 += a0.y + q.x*a1.y + q.y*a2.y;
    cx0 += a0.x + qxx*a1.x + q.y*a2.x;
    cx1 += a0.y + qxx*a1.y + q.y*a2.y;
    cy0 += a0.x + q.x*a1.x + qyy*a2.x;
    cy1 += a0.y + q.x*a1.y + qyy*a2.y;
    const float inv = 1.0f/STEP;
    float a_=(cx0-c00)*inv, b_=(cx1-c01)*inv;
    float c_=(cy0-c00)*inv, d_=(cy1-c01)*inv;
    float2 df=g_delta[idx];
    float  m =g_mask [idx];
    float dn0 = a_*df.x + c_*df.y;
    float dn1 = b_*df.x + d_*df.y;
    int py=p/WW, px=p%WW;
    float gx=gridc(px), gy=gridc(py);
    float o0=(gx+dn0)*m - 2.0f*(1.0f-m);
    float o1=(gy+dn1)*m - 2.0f*(1.0f-m);
    if (idx*2+1 < out_size){
        out[idx*2+0]=o0;
        out[idx*2+1]=o1;
    }
}

// ---------------- launch ---------------------------------------------------
extern "C" void kernel_launch(void* const* d_in, const int* in_sizes, int n_in,
                              void* d_out, int out_size){
    const float* duv = (const float*)d_in[0];
    const float* uv  = (const float*)d_in[1];
    if (n_in >= 2 && in_sizes[0] != 2*HW){
        const float* t=duv; duv=uv; uv=t;
    }
    float* out=(float*)d_out;

    warp_kernel<<<(NN*HW+255)/256,256>>>(duv, uv, out, out_size);
    gather_src_kernel<<<(NN*KC+255)/256,256>>>();
    dim3 gb((NA*NC+255)/256, NN);
    build_kernel<<<gb,256>>>();
    lu_kernel<<<NN,512>>>();
    dim3 ga(HW/256, NN);
    apply_kernel<<<ga,256>>>(out, out_size);
}

// round 10
// speedup vs baseline: 2.0307x; 1.1289x over previous
#include <cuda_runtime.h>
#include <math.h>

#define HH 192
#define WW 192
#define NN 6
#define HW (HH*WW)
#define KGC 20
#define KC 400          /* control points */
#define NA 403          /* system size   */
#define NAP (NA+8)      /* padded rows so GEMM tiles are always full */
#define NC 405          /* cols incl rhs */
#define LD 416          /* padded row stride (floats) */
#define LAMBD 100.0f
#define BIGV 100000000.0f
#define EPSF 1e-9f
#define STEP (2.0f/191.0f)

// ---------------- device scratch (no allocations allowed) ----------------
__device__ float2 g_coord[NN*HW];
__device__ float2 g_delta[NN*HW];
__device__ float  g_mask [NN*HW];
__device__ float2 g_src  [NN*KC];
__device__ float  g_m    [NN*KC];
__device__ __align__(16) float g_A[NN][NAP*LD];   // padded: rows NA..NAP-1 are scratch
__device__ float2 g_wgt[NN*KC];
__device__ float2 g_aff[NN*3];

__device__ __forceinline__ float gridc(int i){ return -1.0f + (float)i*STEP; }
__device__ __forceinline__ int ctrl_i(int t){
    return (int)rintf((float)t * ((float)(HH-1)/(float)(KGC-1)));
}

// ---------------- 1) backward warp (delta/coord/mask on the fly) ----------
__global__ void warp_kernel(const float* __restrict__ duv,
                            const float* __restrict__ uv,
                            float* __restrict__ out, int out_size){
    int idx = blockIdx.x*blockDim.x + threadIdx.x;
    if (idx >= NN*HW) return;
    float u = uv[idx*2+0], v = uv[idx*2+1];
    float x = (u + 1.0f)*0.5f*(float)(WW-1);
    float y = (v + 1.0f)*0.5f*(float)(HH-1);
    float x0 = floorf(x), y0 = floorf(y);
    float wx = x - x0, wy = y - y0;
    float d0=0.f,d1=0.f,c0=0.f,c1=0.f,mk=0.f;
    #pragma unroll
    for (int cy=0; cy<2; cy++){
        #pragma unroll
        for (int cx=0; cx<2; cx++){
            float fx = x0 + (float)cx, fy = y0 + (float)cy;
            float w  = (cx? wx : 1.0f-wx)*(cy? wy : 1.0f-wy);
            if (fx>=0.f && fx<=(float)(WW-1) && fy>=0.f && fy<=(float)(HH-1)){
                int xi=(int)fx, yi=(int)fy;
                float gx=gridc(xi), gy=gridc(yi);
                float du0=duv[(yi*WW+xi)*2+0], du1=duv[(yi*WW+xi)*2+1];
                float vd=(fabsf(du0)<=1.0f && fabsf(du1)<=1.0f)?1.0f:0.0f;
                d0 += w*(du0-gx)*vd;  d1 += w*(du1-gy)*vd;
                c0 += w*gx;           c1 += w*gy;
                mk += w*vd;
            }
        }
    }
    g_coord[idx]=make_float2(c0,c1);
    g_delta[idx]=make_float2(d0,d1);
    float mb=(mk>0.5f)?1.0f:0.0f;
    g_mask[idx]=mb;
    int moff = NN*HW*2 + idx;
    if (moff < out_size) out[moff]=mb;
}

// ---------------- 2) gather control points ---------------------------------
__global__ void gather_src_kernel(){
    int t = blockIdx.x*blockDim.x + threadIdx.x;
    if (t >= NN*KC) return;
    int n=t/KC, k=t%KC;
    int ii=ctrl_i(k/KGC), jj=ctrl_i(k%KGC);
    int p = ii*WW + jj;
    g_src[t]=g_coord[n*HW+p];
    g_m[t]  =g_mask [n*HW+p];
}

// ---------------- 3) build augmented systems (pad rows zeroed) -------------
__global__ void build_kernel(){
    int n = blockIdx.y;
    int e = blockIdx.x*blockDim.x + threadIdx.x;
    if (e >= NAP*NC) return;
    int i=e/NC, j=e%NC;
    float v;
    if (i >= NA){ v = 0.0f; }
    else if (j < KC){
        if (i < KC){
            float2 si=g_src[n*KC+i], sj=g_src[n*KC+j];
            float ddx=si.x-sj.x, ddy=si.y-sj.y;
            float r2=ddx*ddx+ddy*ddy;
            v = 0.5f*r2*logf(r2+EPSF);
            if (i==j) v += LAMBD + BIGV*(1.0f-g_m[n*KC+i]);
        } else {
            float2 sj=g_src[n*KC+j];
            v = (i==KC)?1.0f:((i==KC+1)?sj.x:sj.y);
        }
    } else if (j < NA){
        if (i < KC){
            float2 si=g_src[n*KC+i];
            v = (j==KC)?1.0f:((j==KC+1)?si.x:si.y);
        } else v = 0.0f;
    } else {
        if (i < KC){
            int ii=ctrl_i(i/KGC), jj=ctrl_i(i%KGC);
            v = (j==NA)? gridc(jj) : gridc(ii);
        } else v = 0.0f;
    }
    g_A[n][i*LD+j]=v;
}

// ------- 4) blocked LU, NO PIVOTING on rows 0..399 (diag >= lambda=100) ----
//            final 3x3 bordered Schur block solved with full pivoting.
//            Trailing GEMM: padded full 8-row tiles, unconditional batched
//            C loads (MLP=8) -- no control-dependent loads in the hot loop.
__global__ __launch_bounds__(512,1) void lu_kernel(){
    const int n = blockIdx.x;
    float* __restrict__ A = g_A[n];
    const int tid=threadIdx.x, lane=tid&31, wid=tid>>5;
    __shared__ float SP[NAP][9];                // panel (stride 9: conflict-free)
    __shared__ __align__(16) float sU[8][400];  // staged U12 strip
    __shared__ float s_invd[8];
    __shared__ float sx0[NA], sx1[NA];

    for (int kb=0; kb<400; kb+=8){
        const int c0c  = kb+8;
        const int ncols= NC-c0c;
        const int nrows= NA-c0c;

        // ---- load panel (cols kb..kb+7, rows kb..NAP-1) into SMEM
        for (int i=kb+tid; i<NAP; i+=512){
            const float4* pr=(const float4*)&A[i*LD+kb];
            float4 p0=pr[0], p1=pr[1];
            SP[i][0]=p0.x; SP[i][1]=p0.y; SP[i][2]=p0.z; SP[i][3]=p0.w;
            SP[i][4]=p1.x; SP[i][5]=p1.y; SP[i][6]=p1.z; SP[i][7]=p1.w;
        }
        __syncthreads();

        // ---- factor 8x8 diagonal block in registers (warp 0, lanes 0-7)
        if (wid==0 && lane<8){
            float d[8];
            #pragma unroll
            for (int c=0;c<8;c++) d[c]=SP[kb+lane][c];
            #pragma unroll
            for (int k=0;k<8;k++){
                float ukk = __shfl_sync(0xFFu, d[k], k);
                float inv = 1.0f/ukk;
                if (lane==k) s_invd[k]=inv;
                float l = d[k]*inv;
                bool below = lane>k;
                if (below) d[k]=l;
                #pragma unroll
                for (int j=0;j<8;j++){
                    if (j>k){
                        float ukj = __shfl_sync(0xFFu, d[j], k);
                        if (below) d[j]=fmaf(-l,ukj,d[j]);
                    }
                }
            }
            #pragma unroll
            for (int c=0;c<8;c++) SP[kb+lane][c]=d[c];
        }
        __syncthreads();

        // cache diag inverses
        const float i0=s_invd[0],i1=s_invd[1],i2=s_invd[2],i3=s_invd[3];
        const float i4=s_invd[4],i5=s_invd[5],i6=s_invd[6],i7=s_invd[7];

        // ---- L21 rows (incl pad rows; pad rows are all-zero -> L=0), parallel
        for (int i=c0c+tid; i<NAP; i+=512){
            float a0=SP[i][0],a1=SP[i][1],a2=SP[i][2],a3=SP[i][3];
            float a4=SP[i][4],a5=SP[i][5],a6=SP[i][6],a7=SP[i][7];
            float l0=a0*i0;
            float l1=(a1-l0*SP[kb+0][1])*i1;
            float l2=(a2-l0*SP[kb+0][2]-l1*SP[kb+1][2])*i2;
            float l3=(a3-l0*SP[kb+0][3]-l1*SP[kb+1][3]-l2*SP[kb+2][3])*i3;
            float l4=(a4-l0*SP[kb+0][4]-l1*SP[kb+1][4]-l2*SP[kb+2][4]-l3*SP[kb+3][4])*i4;
            float l5=(a5-l0*SP[kb+0][5]-l1*SP[kb+1][5]-l2*SP[kb+2][5]-l3*SP[kb+3][5]-l4*SP[kb+4][5])*i5;
            float l6=(a6-l0*SP[kb+0][6]-l1*SP[kb+1][6]-l2*SP[kb+2][6]-l3*SP[kb+3][6]-l4*SP[kb+4][6]-l5*SP[kb+5][6])*i6;
            float l7=(a7-l0*SP[kb+0][7]-l1*SP[kb+1][7]-l2*SP[kb+2][7]-l3*SP[kb+3][7]-l4*SP[kb+4][7]-l5*SP[kb+5][7]-l6*SP[kb+6][7])*i7;
            SP[i][0]=l0; SP[i][1]=l1; SP[i][2]=l2; SP[i][3]=l3;
            SP[i][4]=l4; SP[i][5]=l5; SP[i][6]=l6; SP[i][7]=l7;
            float4* pr=(float4*)&A[i*LD+kb];
            pr[0]=make_float4(l0,l1,l2,l3);
            pr[1]=make_float4(l4,l5,l6,l7);
        }
        // ---- panel top rows writeback (L11\U11)
        if (tid<8){
            float4* pr=(float4*)&A[(kb+tid)*LD+kb];
            pr[0]=make_float4(SP[kb+tid][0],SP[kb+tid][1],SP[kb+tid][2],SP[kb+tid][3]);
            pr[1]=make_float4(SP[kb+tid][4],SP[kb+tid][5],SP[kb+tid][6],SP[kb+tid][7]);
        }
        // ---- U12 = L11^{-1} A12, one parallel pass; stage into sU
        const int ncp=(ncols+3)&~3;
        for (int j=c0c+tid; j<NC; j+=512){
            float a[8];
            #pragma unroll
            for (int t=0;t<8;t++) a[t]=A[(kb+t)*LD+j];
            #pragma unroll
            for (int t=1;t<8;t++){
                #pragma unroll
                for (int s=0;s<7;s++)
                    if (s<t) a[t]=fmaf(-SP[kb+t][s],a[s],a[t]);
            }
            #pragma unroll
            for (int t=0;t<8;t++){ A[(kb+t)*LD+j]=a[t]; sU[t][j-c0c]=a[t]; }
        }
        for (int j=ncols+tid; j<ncp; j+=512){
            #pragma unroll
            for (int t=0;t<8;t++) sU[t][j]=0.0f;
        }
        __syncthreads();

        // ---- trailing update A22 -= L21 * U12; full 8-row tiles, batched loads
        {
            const int RT=(nrows+7)>>3, CT=ncp>>2;
            for (int tile=tid; tile<RT*CT; tile+=512){
                const int cj=(tile%CT)*4;
                const int ib=c0c+(tile/CT)*8;
                float4 u0=*(const float4*)&sU[0][cj];
                float4 u1=*(const float4*)&sU[1][cj];
                float4 u2=*(const float4*)&sU[2][cj];
                float4 u3=*(const float4*)&sU[3][cj];
                float4 u4=*(const float4*)&sU[4][cj];
                float4 u5=*(const float4*)&sU[5][cj];
                float4 u6=*(const float4*)&sU[6][cj];
                float4 u7=*(const float4*)&sU[7][cj];
                // 8 independent, unconditional C loads -> batched (MLP=8)
                float4 c0=*(float4*)&A[(ib+0)*LD + c0c + cj];
                float4 c1=*(float4*)&A[(ib+1)*LD + c0c + cj];
                float4 c2=*(float4*)&A[(ib+2)*LD + c0c + cj];
                float4 c3=*(float4*)&A[(ib+3)*LD + c0c + cj];
                float4 c4=*(float4*)&A[(ib+4)*LD + c0c + cj];
                float4 c5=*(float4*)&A[(ib+5)*LD + c0c + cj];
                float4 c6=*(float4*)&A[(ib+6)*LD + c0c + cj];
                float4 c7=*(float4*)&A[(ib+7)*LD + c0c + cj];
                #pragma unroll
                for (int r=0;r<8;r++){
                    float4 cc = (r==0)?c0:(r==1)?c1:(r==2)?c2:(r==3)?c3:
                                (r==4)?c4:(r==5)?c5:(r==6)?c6:c7;
                    const float* Lr=SP[ib+r];
                    const float l0=Lr[0],l1=Lr[1],l2=Lr[2],l3=Lr[3];
                    const float l4=Lr[4],l5=Lr[5],l6=Lr[6],l7=Lr[7];
                    cc.x=fmaf(-l0,u0.x,cc.x); cc.x=fmaf(-l1,u1.x,cc.x);
                    cc.x=fmaf(-l2,u2.x,cc.x); cc.x=fmaf(-l3,u3.x,cc.x);
                    cc.x=fmaf(-l4,u4.x,cc.x); cc.x=fmaf(-l5,u5.x,cc.x);
                    cc.x=fmaf(-l6,u6.x,cc.x); cc.x=fmaf(-l7,u7.x,cc.x);
                    cc.y=fmaf(-l0,u0.y,cc.y); cc.y=fmaf(-l1,u1.y,cc.y);
                    cc.y=fmaf(-l2,u2.y,cc.y); cc.y=fmaf(-l3,u3.y,cc.y);
                    cc.y=fmaf(-l4,u4.y,cc.y); cc.y=fmaf(-l5,u5.y,cc.y);
                    cc.y=fmaf(-l6,u6.y,cc.y); cc.y=fmaf(-l7,u7.y,cc.y);
                    cc.z=fmaf(-l0,u0.z,cc.z); cc.z=fmaf(-l1,u1.z,cc.z);
                    cc.z=fmaf(-l2,u2.z,cc.z); cc.z=fmaf(-l3,u3.z,cc.z);
                    cc.z=fmaf(-l4,u4.z,cc.z); cc.z=fmaf(-l5,u5.z,cc.z);
                    cc.z=fmaf(-l6,u6.z,cc.z); cc.z=fmaf(-l7,u7.z,cc.z);
                    cc.w=fmaf(-l0,u0.w,cc.w); cc.w=fmaf(-l1,u1.w,cc.w);
                    cc.w=fmaf(-l2,u2.w,cc.w); cc.w=fmaf(-l3,u3.w,cc.w);
                    cc.w=fmaf(-l4,u4.w,cc.w); cc.w=fmaf(-l5,u5.w,cc.w);
                    cc.w=fmaf(-l6,u6.w,cc.w); cc.w=fmaf(-l7,u7.w,cc.w);
                    *(float4*)&A[(ib+r)*LD + c0c + cj]=cc;
                }
            }
        }
        __syncthreads();
    }

    // ---- final 3x5 bordered block: full-pivot Gauss-Jordan + back-sub
    if (wid==0){
        if (lane==0){
            float M[3][5];
            #pragma unroll
            for (int r=0;r<3;r++)
                #pragma unroll
                for (int c=0;c<5;c++)
                    M[r][c]=A[(400+r)*LD+400+c];
            #pragma unroll
            for (int k=0;k<3;k++){
                int p=k;
                float bv=fabsf(M[k][k]);
                #pragma unroll
                for (int r=0;r<3;r++)
                    if (r>k && fabsf(M[r][k])>bv){bv=fabsf(M[r][k]);p=r;}
                if (p!=k){
                    #pragma unroll
                    for (int c=0;c<5;c++){float t1=M[k][c];M[k][c]=M[p][c];M[p][c]=t1;}
                }
                float inv=1.0f/M[k][k];
                #pragma unroll
                for (int c=0;c<5;c++) M[k][c]*=inv;
                #pragma unroll
                for (int r=0;r<3;r++){
                    if (r!=k){
                        float f=M[r][k];
                        #pragma unroll
                        for (int c=0;c<5;c++) M[r][c]=fmaf(-f,M[k][c],M[r][c]);
                    }
                }
            }
            #pragma unroll
            for (int r=0;r<3;r++){ sx0[400+r]=M[r][3]; sx1[400+r]=M[r][4]; }
        }
        __syncwarp();
        for (int i=399;i>=0;i--){
            float a0=0.f,a1=0.f;
            for (int j=i+1+lane;j<NA;j+=32){
                float aa=A[i*LD+j];
                a0 = fmaf(aa, sx0[j], a0);
                a1 = fmaf(aa, sx1[j], a1);
            }
            #pragma unroll
            for (int o=16;o>0;o>>=1){
                a0 += __shfl_down_sync(0xffffffffu,a0,o);
                a1 += __shfl_down_sync(0xffffffffu,a1,o);
            }
            if (lane==0){
                float dinv=1.0f/A[i*LD+i];
                sx0[i]=(A[i*LD+NA  ]-a0)*dinv;
                sx1[i]=(A[i*LD+NA+1]-a1)*dinv;
            }
            __syncwarp();
        }
    }
    __syncthreads();
    for (int k=tid;k<KC;k+=512) g_wgt[n*KC+k]=make_float2(sx0[k],sx1[k]);
    if (tid<3) g_aff[n*3+tid]=make_float2(sx0[KC+tid],sx1[KC+tid]);
}

// ---------------- 5) TPS apply + Jacobian + final combine ------------------
__global__ __launch_bounds__(256) void apply_kernel(float* __restrict__ out, int out_size){
    int n = blockIdx.y;
    int p = blockIdx.x*256 + threadIdx.x;
    __shared__ float2 s_src[KC];
    __shared__ float2 s_wgt[KC];
    for (int k=threadIdx.x;k<KC;k+=256){
        s_src[k]=g_src[n*KC+k];
        s_wgt[k]=g_wgt[n*KC+k];
    }
    __syncthreads();
    int idx = n*HW + p;
    float2 q = g_coord[idx];
    float c00=0.f,c01=0.f,cx0=0.f,cx1=0.f,cy0=0.f,cy1=0.f;
    #pragma unroll 4
    for (int k=0;k<KC;k++){
        float2 s=s_src[k], wv=s_wgt[k];
        float ddx=q.x-s.x, ddy=q.y-s.y;
        float r20=fmaf(ddx,ddx,ddy*ddy);
        float r2x=fmaf(STEP, fmaf(2.0f,ddx,STEP), r20);
        float r2y=fmaf(STEP, fmaf(2.0f,ddy,STEP), r20);
        float U0=0.5f*r20*__logf(r20+EPSF);
        float Ux=0.5f*r2x*__logf(r2x+EPSF);
        float Uy=0.5f*r2y*__logf(r2y+EPSF);
        c00=fmaf(U0,wv.x,c00); c01=fmaf(U0,wv.y,c01);
        cx0=fmaf(Ux,wv.x,cx0); cx1=fmaf(Ux,wv.y,cx1);
        cy0=fmaf(Uy,wv.x,cy0); cy1=fmaf(Uy,wv.y,cy1);
    }
    float2 a0=g_aff[n*3+0], a1=g_aff[n*3+1], a2=g_aff[n*3+2];
    float qxx=q.x+STEP, qyy=q.y+STEP;
    c00 += a0.x + q.x*a1.x + q.y*a2.x;
    c01 += a0.y + q.x*a1.y + q.y*a2.y;
    cx0 += a0.x + qxx*a1.x + q.y*a2.x;
    cx1 += a0.y + qxx*a1.y + q.y*a2.y;
    cy0 += a0.x + q.x*a1.x + qyy*a2.x;
    cy1 += a0.y + q.x*a1.y + qyy*a2.y;
    const float inv = 1.0f/STEP;
    float a_=(cx0-c00)*inv, b_=(cx1-c01)*inv;
    float c_=(cy0-c00)*inv, d_=(cy1-c01)*inv;
    float2 df=g_delta[idx];
    float  m =g_mask [idx];
    float dn0 = a_*df.x + c_*df.y;
    float dn1 = b_*df.x + d_*df.y;
    int py=p/WW, px=p%WW;
    float gx=gridc(px), gy=gridc(py);
    float o0=(gx+dn0)*m - 2.0f*(1.0f-m);
    float o1=(gy+dn1)*m - 2.0f*(1.0f-m);
    if (idx*2+1 < out_size){
        out[idx*2+0]=o0;
        out[idx*2+1]=o1;
    }
}

// ---------------- launch ---------------------------------------------------
extern "C" void kernel_launch(void* const* d_in, const int* in_sizes, int n_in,
                              void* d_out, int out_size){
    const float* duv = (const float*)d_in[0];
    const float* uv  = (const float*)d_in[1];
    if (n_in >= 2 && in_sizes[0] != 2*HW){
        const float* t=duv; duv=uv; uv=t;
    }
    float* out=(float*)d_out;

    warp_kernel<<<(NN*HW+255)/256,256>>>(duv, uv, out, out_size);
    gather_src_kernel<<<(NN*KC+255)/256,256>>>();
    dim3 gb((NAP*NC+255)/256, NN);
    build_kernel<<<gb,256>>>();
    lu_kernel<<<NN,512>>>();
    dim3 ga(HW/256, NN);
    apply_kernel<<<ga,256>>>(out, out_size);
}

// round 13
// speedup vs baseline: 2.5399x; 1.2508x over previous
#include <cuda_runtime.h>
#include <math.h>

#define HH 192
#define WW 192
#define NN 6
#define HW (HH*WW)
#define KGC 20
#define KC 400          /* control points */
#define NA 403          /* system size   */
#define NAP (NA+8)      /* padded rows so GEMM tiles are always full */
#define NC 405          /* cols incl rhs */
#define NCB 408         /* padded col count (8-col tiles); tiles 0..50 */
#define LD 416          /* padded row stride (floats) */
#define CLUSTER 8
#define LAMBD 100.0f
#define BIGV 100000000.0f
#define EPSF 1e-9f
#define STEP (2.0f/191.0f)

// ---------------- device scratch (no allocations allowed) ----------------
__device__ float2 g_coord[NN*HW];
__device__ float2 g_delta[NN*HW];
__device__ float  g_mask [NN*HW];
__device__ float2 g_src  [NN*KC];
__device__ float  g_m    [NN*KC];
__device__ __align__(16) float g_A[NN][NAP*LD];   // padded rows+cols are scratch
__device__ float2 g_wgt[NN*KC];
__device__ float2 g_aff[NN*3];

__device__ __forceinline__ float gridc(int i){ return -1.0f + (float)i*STEP; }
__device__ __forceinline__ int ctrl_i(int t){
    return (int)rintf((float)t * ((float)(HH-1)/(float)(KGC-1)));
}

// ---------------- 1) backward warp (delta/coord/mask on the fly) ----------
__global__ void warp_kernel(const float* __restrict__ duv,
                            const float* __restrict__ uv,
                            float* __restrict__ out, int out_size){
    int idx = blockIdx.x*blockDim.x + threadIdx.x;
    if (idx >= NN*HW) return;
    float u = uv[idx*2+0], v = uv[idx*2+1];
    float x = (u + 1.0f)*0.5f*(float)(WW-1);
    float y = (v + 1.0f)*0.5f*(float)(HH-1);
    float x0 = floorf(x), y0 = floorf(y);
    float wx = x - x0, wy = y - y0;
    float d0=0.f,d1=0.f,c0=0.f,c1=0.f,mk=0.f;
    #pragma unroll
    for (int cy=0; cy<2; cy++){
        #pragma unroll
        for (int cx=0; cx<2; cx++){
            float fx = x0 + (float)cx, fy = y0 + (float)cy;
            float w  = (cx? wx : 1.0f-wx)*(cy? wy : 1.0f-wy);
            if (fx>=0.f && fx<=(float)(WW-1) && fy>=0.f && fy<=(float)(HH-1)){
                int xi=(int)fx, yi=(int)fy;
                float gx=gridc(xi), gy=gridc(yi);
                float du0=duv[(yi*WW+xi)*2+0], du1=duv[(yi*WW+xi)*2+1];
                float vd=(fabsf(du0)<=1.0f && fabsf(du1)<=1.0f)?1.0f:0.0f;
                d0 += w*(du0-gx)*vd;  d1 += w*(du1-gy)*vd;
                c0 += w*gx;           c1 += w*gy;
                mk += w*vd;
            }
        }
    }
    g_coord[idx]=make_float2(c0,c1);
    g_delta[idx]=make_float2(d0,d1);
    float mb=(mk>0.5f)?1.0f:0.0f;
    g_mask[idx]=mb;
    int moff = NN*HW*2 + idx;
    if (moff < out_size) out[moff]=mb;
}

// ---------------- 2) gather control points ---------------------------------
__global__ void gather_src_kernel(){
    int t = blockIdx.x*blockDim.x + threadIdx.x;
    if (t >= NN*KC) return;
    int n=t/KC, k=t%KC;
    int ii=ctrl_i(k/KGC), jj=ctrl_i(k%KGC);
    int p = ii*WW + jj;
    g_src[t]=g_coord[n*HW+p];
    g_m[t]  =g_mask [n*HW+p];
}

// ------- 3) build augmented systems (pad rows AND pad cols zeroed) ---------
__global__ void build_kernel(){
    int n = blockIdx.y;
    int e = blockIdx.x*blockDim.x + threadIdx.x;
    if (e >= NAP*NCB) return;
    int i=e/NCB, j=e%NCB;
    float v;
    if (i >= NA || j >= NC){ v = 0.0f; }
    else if (j < KC){
        if (i < KC){
            float2 si=g_src[n*KC+i], sj=g_src[n*KC+j];
            float ddx=si.x-sj.x, ddy=si.y-sj.y;
            float r2=ddx*ddx+ddy*ddy;
            v = 0.5f*r2*logf(r2+EPSF);
            if (i==j) v += LAMBD + BIGV*(1.0f-g_m[n*KC+i]);
        } else {
            float2 sj=g_src[n*KC+j];
            v = (i==KC)?1.0f:((i==KC+1)?sj.x:sj.y);
        }
    } else if (j < NA){
        if (i < KC){
            float2 si=g_src[n*KC+i];
            v = (j==KC)?1.0f:((j==KC+1)?si.x:si.y);
        } else v = 0.0f;
    } else {
        if (i < KC){
            int ii=ctrl_i(i/KGC), jj=ctrl_i(i%KGC);
            v = (j==NA)? gridc(jj) : gridc(ii);
        } else v = 0.0f;
    }
    g_A[n][i*LD+j]=v;
}

// ------- 4) cluster-parallel blocked LU, NO PIVOTING on rows 0..399 --------
//            8 CTAs per matrix; columns split in 8-col tiles, owner=(col/8)&7.
//            Panel load + 8x8 factor + L21 replicated per CTA (SMEM only);
//            U12 + trailing update done by column owner; 1 cluster.sync/panel.
//            Cross-CTA reads use __ldcg (L1 bypass): 128B L1 lines span
//            neighboring tiles, and the inline cluster barrier does not
//            guarantee an L1D invalidate.
__global__ __launch_bounds__(512,1) __cluster_dims__(CLUSTER,1,1)
void lu_kernel(){
    const int n    = blockIdx.x / CLUSTER;
    const int rank = blockIdx.x % CLUSTER;
    float* __restrict__ A = g_A[n];
    const int tid=threadIdx.x, lane=tid&31, wid=tid>>5;
    __shared__ float SP[NAP][9];               // panel (stride 9: conflict-free)
    __shared__ __align__(16) float sU[8][64];  // owned U12 cols, packed (<=7 tiles)
    __shared__ int   s_tcol[8];                // owned tile -> global col base
    __shared__ int   s_nt;
    __shared__ float s_invd[8];
    __shared__ float sx0[NA], sx1[NA];

    for (int kb=0; kb<400; kb+=8){
        const int c0c = kb+8;

        // ---- load panel (cols kb..kb+7, rows kb..NAP-1); cross-CTA -> .cg
        for (int i=kb+tid; i<NAP; i+=512){
            const float4* pr=(const float4*)&A[i*LD+kb];
            float4 p0=__ldcg(pr+0), p1=__ldcg(pr+1);
            SP[i][0]=p0.x; SP[i][1]=p0.y; SP[i][2]=p0.z; SP[i][3]=p0.w;
            SP[i][4]=p1.x; SP[i][5]=p1.y; SP[i][6]=p1.z; SP[i][7]=p1.w;
        }
        __syncthreads();

        // ---- factor 8x8 diagonal block in registers (warp 0, lanes 0-7)
        if (wid==0 && lane<8){
            float d[8];
            #pragma unroll
            for (int c=0;c<8;c++) d[c]=SP[kb+lane][c];
            #pragma unroll
            for (int k=0;k<8;k++){
                float ukk = __shfl_sync(0xFFu, d[k], k);
                float inv = 1.0f/ukk;
                if (lane==k) s_invd[k]=inv;
                float l = d[k]*inv;
                bool below = lane>k;
                if (below) d[k]=l;
                #pragma unroll
                for (int j=0;j<8;j++){
                    if (j>k){
                        float ukj = __shfl_sync(0xFFu, d[j], k);
                        if (below) d[j]=fmaf(-l,ukj,d[j]);
                    }
                }
            }
            #pragma unroll
            for (int c=0;c<8;c++) SP[kb+lane][c]=d[c];
        }
        // meanwhile: thread 511 (warp 15) builds owned-tile list
        if (tid==511){
            int cnt=0;
            for (int T=c0c>>3; T<=50; T++)
                if ((T&7)==rank) s_tcol[cnt++]=T<<3;
            s_nt=cnt;
        }
        __syncthreads();

        // ---- U11 writeback (rank 0 only; needed for back-substitution)
        if (rank==0 && tid<8){
            float4* pr=(float4*)&A[(kb+tid)*LD+kb];
            pr[0]=make_float4(SP[kb+tid][0],SP[kb+tid][1],SP[kb+tid][2],SP[kb+tid][3]);
            pr[1]=make_float4(SP[kb+tid][4],SP[kb+tid][5],SP[kb+tid][6],SP[kb+tid][7]);
        }

        const float i0=s_invd[0],i1=s_invd[1],i2=s_invd[2],i3=s_invd[3];
        const float i4=s_invd[4],i5=s_invd[5],i6=s_invd[6],i7=s_invd[7];
        const int nt = s_nt;

        // ---- L21 all rows, SMEM only (never needed in global)
        for (int i=c0c+tid; i<NAP; i+=512){
            float a0=SP[i][0],a1=SP[i][1],a2=SP[i][2],a3=SP[i][3];
            float a4=SP[i][4],a5=SP[i][5],a6=SP[i][6],a7=SP[i][7];
            float l0=a0*i0;
            float l1=(a1-l0*SP[kb+0][1])*i1;
            float l2=(a2-l0*SP[kb+0][2]-l1*SP[kb+1][2])*i2;
            float l3=(a3-l0*SP[kb+0][3]-l1*SP[kb+1][3]-l2*SP[kb+2][3])*i3;
            float l4=(a4-l0*SP[kb+0][4]-l1*SP[kb+1][4]-l2*SP[kb+2][4]-l3*SP[kb+3][4])*i4;
            float l5=(a5-l0*SP[kb+0][5]-l1*SP[kb+1][5]-l2*SP[kb+2][5]-l3*SP[kb+3][5]-l4*SP[kb+4][5])*i5;
            float l6=(a6-l0*SP[kb+0][6]-l1*SP[kb+1][6]-l2*SP[kb+2][6]-l3*SP[kb+3][6]-l4*SP[kb+4][6]-l5*SP[kb+5][6])*i6;
            float l7=(a7-l0*SP[kb+0][7]-l1*SP[kb+1][7]-l2*SP[kb+2][7]-l3*SP[kb+3][7]-l4*SP[kb+4][7]-l5*SP[kb+5][7]-l6*SP[kb+6][7])*i7;
            SP[i][0]=l0; SP[i][1]=l1; SP[i][2]=l2; SP[i][3]=l3;
            SP[i][4]=l4; SP[i][5]=l5; SP[i][6]=l6; SP[i][7]=l7;
        }

        // ---- U12 for owned columns only (write global for back-sub + stage sU)
        for (int c=tid; c<nt*8; c+=512){
            int j = s_tcol[c>>3] + (c&7);
            float a[8];
            #pragma unroll
            for (int t=0;t<8;t++) a[t]=__ldcg(&A[(kb+t)*LD+j]);
            #pragma unroll
            for (int t=1;t<8;t++){
                #pragma unroll
                for (int s=0;s<7;s++)
                    if (s<t) a[t]=fmaf(-SP[kb+t][s],a[s],a[t]);
            }
            #pragma unroll
            for (int t=0;t<8;t++){ A[(kb+t)*LD+j]=a[t]; sU[t][c]=a[t]; }
        }
        __syncthreads();

        // ---- trailing update (owned columns): C -= L21 * U12, batched loads
        {
            const int nrows = NA - c0c;
            const int RT=(nrows+7)>>3;
            const int NCk=nt*2;                 // packed float4 chunks
            for (int u=tid; u<RT*NCk; u+=512){
                const int ck = u % NCk;
                const int ib = c0c + (u/NCk)*8;
                const int pc = ck*4;
                const int gj = s_tcol[ck>>1] + (ck&1)*4;
                float4 u0=*(const float4*)&sU[0][pc];
                float4 u1=*(const float4*)&sU[1][pc];
                float4 u2=*(const float4*)&sU[2][pc];
                float4 u3=*(const float4*)&sU[3][pc];
                float4 u4=*(const float4*)&sU[4][pc];
                float4 u5=*(const float4*)&sU[5][pc];
                float4 u6=*(const float4*)&sU[6][pc];
                float4 u7=*(const float4*)&sU[7][pc];
                float4 c0=__ldcg((const float4*)&A[(ib+0)*LD + gj]);
                float4 c1=__ldcg((const float4*)&A[(ib+1)*LD + gj]);
                float4 c2=__ldcg((const float4*)&A[(ib+2)*LD + gj]);
                float4 c3=__ldcg((const float4*)&A[(ib+3)*LD + gj]);
                float4 c4=__ldcg((const float4*)&A[(ib+4)*LD + gj]);
                float4 c5=__ldcg((const float4*)&A[(ib+5)*LD + gj]);
                float4 c6=__ldcg((const float4*)&A[(ib+6)*LD + gj]);
                float4 c7=__ldcg((const float4*)&A[(ib+7)*LD + gj]);
                #pragma unroll
                for (int r=0;r<8;r++){
                    float4 cc = (r==0)?c0:(r==1)?c1:(r==2)?c2:(r==3)?c3:
                                (r==4)?c4:(r==5)?c5:(r==6)?c6:c7;
                    const float* Lr=SP[ib+r];
                    const float l0=Lr[0],l1=Lr[1],l2=Lr[2],l3=Lr[3];
                    const float l4=Lr[4],l5=Lr[5],l6=Lr[6],l7=Lr[7];
                    cc.x=fmaf(-l0,u0.x,cc.x); cc.x=fmaf(-l1,u1.x,cc.x);
                    cc.x=fmaf(-l2,u2.x,cc.x); cc.x=fmaf(-l3,u3.x,cc.x);
                    cc.x=fmaf(-l4,u4.x,cc.x); cc.x=fmaf(-l5,u5.x,cc.x);
                    cc.x=fmaf(-l6,u6.x,cc.x); cc.x=fmaf(-l7,u7.x,cc.x);
                    cc.y=fmaf(-l0,u0.y,cc.y); cc.y=fmaf(-l1,u1.y,cc.y);
                    cc.y=fmaf(-l2,u2.y,cc.y); cc.y=fmaf(-l3,u3.y,cc.y);
                    cc.y=fmaf(-l4,u4.y,cc.y); cc.y=fmaf(-l5,u5.y,cc.y);
                    cc.y=fmaf(-l6,u6.y,cc.y); cc.y=fmaf(-l7,u7.y,cc.y);
                    cc.z=fmaf(-l0,u0.z,cc.z); cc.z=fmaf(-l1,u1.z,cc.z);
                    cc.z=fmaf(-l2,u2.z,cc.z); cc.z=fmaf(-l3,u3.z,cc.z);
                    cc.z=fmaf(-l4,u4.z,cc.z); cc.z=fmaf(-l5,u5.z,cc.z);
                    cc.z=fmaf(-l6,u6.z,cc.z); cc.z=fmaf(-l7,u7.z,cc.z);
                    cc.w=fmaf(-l0,u0.w,cc.w); cc.w=fmaf(-l1,u1.w,cc.w);
                    cc.w=fmaf(-l2,u2.w,cc.w); cc.w=fmaf(-l3,u3.w,cc.w);
                    cc.w=fmaf(-l4,u4.w,cc.w); cc.w=fmaf(-l5,u5.w,cc.w);
                    cc.w=fmaf(-l6,u6.w,cc.w); cc.w=fmaf(-l7,u7.w,cc.w);
                    *(float4*)&A[(ib+r)*LD + gj]=cc;
                }
            }
        }
        // ---- cluster barrier: release trailing writes to L2
        asm volatile("barrier.cluster.arrive.aligned;" ::: "memory");
        asm volatile("barrier.cluster.wait.aligned;"   ::: "memory");
    }

    // ---- rank 0 of each matrix: 3x3 bordered block + back-substitution
    //      (reads other CTAs' U12 -> all .cg)
    if (rank==0){
        if (wid==0){
            if (lane==0){
                float M[3][5];
                #pragma unroll
                for (int r=0;r<3;r++)
                    #pragma unroll
                    for (int c=0;c<5;c++)
                        M[r][c]=__ldcg(&A[(400+r)*LD+400+c]);
                #pragma unroll
                for (int k=0;k<3;k++){
                    int p=k;
                    float bv=fabsf(M[k][k]);
                    #pragma unroll
                    for (int r=0;r<3;r++)
                        if (r>k && fabsf(M[r][k])>bv){bv=fabsf(M[r][k]);p=r;}
                    if (p!=k){
                        #pragma unroll
                        for (int c=0;c<5;c++){float t1=M[k][c];M[k][c]=M[p][c];M[p][c]=t1;}
                    }
                    float inv=1.0f/M[k][k];
                    #pragma unroll
                    for (int c=0;c<5;c++) M[k][c]*=inv;
                    #pragma unroll
                    for (int r=0;r<3;r++){
                        if (r!=k){
                            float f=M[r][k];
                            #pragma unroll
                            for (int c=0;c<5;c++) M[r][c]=fmaf(-f,M[k][c],M[r][c]);
                        }
                    }
                }
                #pragma unroll
                for (int r=0;r<3;r++){ sx0[400+r]=M[r][3]; sx1[400+r]=M[r][4]; }
            }
            __syncwarp();
            for (int i=399;i>=0;i--){
                float a0=0.f,a1=0.f;
                for (int j=i+1+lane;j<NA;j+=32){
                    float aa=__ldcg(&A[i*LD+j]);
                    a0 = fmaf(aa, sx0[j], a0);
                    a1 = fmaf(aa, sx1[j], a1);
                }
                #pragma unroll
                for (int o=16;o>0;o>>=1){
                    a0 += __shfl_down_sync(0xffffffffu,a0,o);
                    a1 += __shfl_down_sync(0xffffffffu,a1,o);
                }
                if (lane==0){
                    float dinv=1.0f/__ldcg(&A[i*LD+i]);
                    sx0[i]=(__ldcg(&A[i*LD+NA  ])-a0)*dinv;
                    sx1[i]=(__ldcg(&A[i*LD+NA+1])-a1)*dinv;
                }
                __syncwarp();
            }
        }
        __syncthreads();
        for (int k=tid;k<KC;k+=512) g_wgt[n*KC+k]=make_float2(sx0[k],sx1[k]);
        if (tid<3) g_aff[n*3+tid]=make_float2(sx0[KC+tid],sx1[KC+tid]);
    }
}

// ---------------- 5) TPS apply + Jacobian + final combine ------------------
__global__ __launch_bounds__(256) void apply_kernel(float* __restrict__ out, int out_size){
    int n = blockIdx.y;
    int p = blockIdx.x*256 + threadIdx.x;
    __shared__ float2 s_src[KC];
    __shared__ float2 s_wgt[KC];
    for (int k=threadIdx.x;k<KC;k+=256){
        s_src[k]=g_src[n*KC+k];
        s_wgt[k]=g_wgt[n*KC+k];
    }
    __syncthreads();
    int idx = n*HW + p;
    float2 q = g_coord[idx];
    float c00=0.f,c01=0.f,cx0=0.f,cx1=0.f,cy0=0.f,cy1=0.f;
    #pragma unroll 4
    for (int k=0;k<KC;k++){
        float2 s=s_src[k], wv=s_wgt[k];
        float ddx=q.x-s.x, ddy=q.y-s.y;
        float r20=fmaf(ddx,ddx,ddy*ddy);
        float r2x=fmaf(STEP, fmaf(2.0f,ddx,STEP), r20);
        float r2y=fmaf(STEP, fmaf(2.0f,ddy,STEP), r20);
        float U0=0.5f*r20*__logf(r20+EPSF);
        float Ux=0.5f*r2x*__logf(r2x+EPSF);
        float Uy=0.5f*r2y*__logf(r2y+EPSF);
        c00=fmaf(U0,wv.x,c00); c01=fmaf(U0,wv.y,c01);
        cx0=fmaf(Ux,wv.x,cx0); cx1=fmaf(Ux,wv.y,cx1);
        cy0=fmaf(Uy,wv.x,cy0); cy1=fmaf(Uy,wv.y,cy1);
    }
    float2 a0=g_aff[n*3+0], a1=g_aff[n*3+1], a2=g_aff[n*3+2];
    float qxx=q.x+STEP, qyy=q.y+STEP;
    c00 += a0.x + q.x*a1.x + q.y*a2.x;
    c01 += a0.y + q.x*a1.y + q.y*a2.y;
    cx0 += a0.x + qxx*a1.x + q.y*a2.x;
    cx1 += a0.y + qxx*a1.y + q.y*a2.y;
    cy0 += a0.x + q.x*a1.x + qyy*a2.x;
    cy1 += a0.y + q.x*a1.y + qyy*a2.y;
    const float inv = 1.0f/STEP;
    float a_=(cx0-c00)*inv, b_=(cx1-c01)*inv;
    float c_=(cy0-c00)*inv, d_=(cy1-c01)*inv;
    float2 df=g_delta[idx];
    float  m =g_mask [idx];
    float dn0 = a_*df.x + c_*df.y;
    float dn1 = b_*df.x + d_*df.y;
    int py=p/WW, px=p%WW;
    float gx=gridc(px), gy=gridc(py);
    float o0=(gx+dn0)*m - 2.0f*(1.0f-m);
    float o1=(gy+dn1)*m - 2.0f*(1.0f-m);
    if (idx*2+1 < out_size){
        out[idx*2+0]=o0;
        out[idx*2+1]=o1;
    }
}

// ---------------- launch ---------------------------------------------------
extern "C" void kernel_launch(void* const* d_in, const int* in_sizes, int n_in,
                              void* d_out, int out_size){
    const float* duv = (const float*)d_in[0];
    const float* uv  = (const float*)d_in[1];
    if (n_in >= 2 && in_sizes[0] != 2*HW){
        const float* t=duv; duv=uv; uv=t;
    }
    float* out=(float*)d_out;

    warp_kernel<<<(NN*HW+255)/256,256>>>(duv, uv, out, out_size);
    gather_src_kernel<<<(NN*KC+255)/256,256>>>();
    dim3 gb((NAP*NCB+255)/256, NN);
    build_kernel<<<gb,256>>>();
    lu_kernel<<<NN*CLUSTER,512>>>();
    dim3 ga(HW/256, NN);
    apply_kernel<<<ga,256>>>(out, out_size);
}